// round 9
// baseline (speedup 1.0000x reference)
#include <cuda_runtime.h>
#include <math.h>

// Problem constants
#define Nn   4096
#define Qq   2048
#define LDIM 8192
#define NB   64
#define NP   (Qq/NB)   // 32

#define EULERC 0.5772156649015329
#define CC     0.7796968012336761   // sqrt(6)/pi
#define C2C    0.6079271018540267   // 6/pi^2
#define ZSCALE 16777216.0f          // 2^24 fixed-point scale for deterministic sums

// ---------------- device scratch (static, allocation-free) ----------------
__device__ float  g_zs[Nn];
__device__ double g_sums[3];
__device__ int    g_cnt[Qq];
__device__ unsigned long long g_tsum[Qq];
__device__ float  g_t[Qq];
__device__ float  g_x[Qq];
// (Qq+1) rows x Qq cols: row Qq holds the rhs r, becomes y = L^{-1} r after sweep
__device__ float  g_A[(size_t)(Qq + 1) * Qq];
__device__ double g_logdiag[NP];
// dataflow flags
__device__ int    g_fL;                   // L(s) published <=> g_fL >= s+1
__device__ int    g_ftr[NP + 1];          // trsm of tile bx done for col kb <=> >= kb+1
__device__ int    g_gen[(NP + 1) * NP];   // #syrk updates applied to tile (bx,by)

// ---------------- helpers ----------------
__device__ __forceinline__ double block_reduce_d(double v, double* sbuf) {
    int t = threadIdx.x;
    sbuf[t] = v;
    __syncthreads();
    for (int s = blockDim.x >> 1; s > 0; s >>= 1) {
        if (t < s) sbuf[t] += sbuf[t + s];
        __syncthreads();
    }
    double r = sbuf[0];
    __syncthreads();
    return r;
}

__device__ __forceinline__ void wait_eq(int* p, int v, int ns) {
    if (threadIdx.x == 0) {
        while (atomicAdd(p, 0) != v) __nanosleep(ns);
        __threadfence();
    }
    __syncthreads();
}
__device__ __forceinline__ void wait_ge(int* p, int v, int ns) {
    if (threadIdx.x == 0) {
        while (atomicAdd(p, 0) < v) __nanosleep(ns);
        __threadfence();
    }
    __syncthreads();
}
__device__ __forceinline__ void publish(int* p, int v) {
    __threadfence();
    __syncthreads();
    if (threadIdx.x == 0) atomicExch(p, v);
}

// 64x64 Cholesky of tile in shared S; L written to gout (ld=Qq; upper triangle
// garbage by design) AND back into S. Raw-column variant.
__device__ void potf2_core(float S[64][65], float buf[2][64], float* ds,
                           float* gout, int logidx) {
    int t = threadIdx.x;
    int tcol = t & 63;
    int rbase = (t >> 6) * 16;
    float c[16];
#pragma unroll
    for (int i = 0; i < 16; i++) c[i] = S[rbase + i][tcol];
    if (tcol == 0) {
#pragma unroll
        for (int i = 0; i < 16; i++) buf[0][rbase + i] = c[i];
    }
    __syncthreads();
    for (int j = 0; j < 64; j++) {
        float* bc = buf[j & 1];
        if (t == 0) ds[j] = bc[j];
        if (tcol > j) {
            float fr = bc[tcol] * __frcp_rn(bc[j]);
#pragma unroll
            for (int i = 0; i < 16; i++) c[i] -= fr * bc[rbase + i];
            if (tcol == j + 1) {
#pragma unroll
                for (int i = 0; i < 16; i++) buf[(j + 1) & 1][rbase + i] = c[i];
            }
        }
        __syncthreads();
    }
    float r = rsqrtf(ds[tcol]);
#pragma unroll
    for (int i = 0; i < 16; i++) {
        float v = c[i] * r;
        gout[(size_t)(rbase + i) * Qq + tcol] = v;
        S[rbase + i][tcol] = v;
    }
    if (t < 64) {
        float lg = logf(ds[tcol]);
#pragma unroll
        for (int off = 16; off > 0; off >>= 1)
            lg += __shfl_down_sync(0xffffffffu, lg, off);
        if ((t & 31) == 0) buf[1][t >> 5] = lg;
    }
    __syncthreads();
    if (t == 0)
        g_logdiag[logidx] = 0.5 * ((double)buf[1][0] + (double)buf[1][1]);
    __syncthreads();
}

// forward substitution of 64 rows in X against lower-tri Ld (rd = 1/diag)
__device__ __forceinline__ void trsm64(float (*Ld)[65], float (*X)[65],
                                       const float* rd) {
    int tid = threadIdx.x;
    if (tid < 64) {
        float x[64];
#pragma unroll
        for (int c = 0; c < 64; c++) x[c] = X[tid][c];
#pragma unroll
        for (int c = 0; c < 64; c++) {
            float a0 = 0.f, a1 = 0.f, a2 = 0.f, a3 = 0.f;
#pragma unroll
            for (int p = 0; p < c; p += 4) {
                a0 += x[p] * Ld[c][p];
                if (p + 1 < c) a1 += x[p + 1] * Ld[c][p + 1];
                if (p + 2 < c) a2 += x[p + 2] * Ld[c][p + 2];
                if (p + 3 < c) a3 += x[p + 3] * Ld[c][p + 3];
            }
            x[c] = (x[c] - ((a0 + a1) + (a2 + a3))) * rd[c];
        }
#pragma unroll
        for (int c = 0; c < 64; c++) X[tid][c] = x[c];
    }
}

// 64x64x64 A*B^T accumulate: acc[4][4] per thread (16x16 grid of threads)
__device__ __forceinline__ void syrk_acc(float (*Pa)[65], float (*Pb)[65],
                                         float acc[4][4]) {
    int ty = threadIdx.x >> 4, tx = threadIdx.x & 15;
#pragma unroll
    for (int i = 0; i < 4; i++)
#pragma unroll
        for (int j = 0; j < 4; j++) acc[i][j] = 0.0f;
#pragma unroll 8
    for (int k = 0; k < 64; k++) {
        float a0 = Pa[ty * 4 + 0][k], a1 = Pa[ty * 4 + 1][k];
        float a2 = Pa[ty * 4 + 2][k], a3 = Pa[ty * 4 + 3][k];
        float b0 = Pb[tx * 4 + 0][k], b1 = Pb[tx * 4 + 1][k];
        float b2 = Pb[tx * 4 + 2][k], b3 = Pb[tx * 4 + 3][k];
        acc[0][0] += a0 * b0; acc[0][1] += a0 * b1; acc[0][2] += a0 * b2; acc[0][3] += a0 * b3;
        acc[1][0] += a1 * b0; acc[1][1] += a1 * b1; acc[1][2] += a1 * b2; acc[1][3] += a1 * b3;
        acc[2][0] += a2 * b0; acc[2][1] += a2 * b1; acc[2][2] += a2 * b2; acc[2][3] += a2 * b3;
        acc[3][0] += a3 * b0; acc[3][1] += a3 * b1; acc[3][2] += a3 * b2; acc[3][3] += a3 * b3;
    }
}

// load/store 64x64 tile (row-guarded vs Qq+1 rows)
__device__ __forceinline__ void load_tile(float (*S)[65], int bx, int colblk) {
    int tid = threadIdx.x;
    const float* base = g_A + (size_t)(bx * 64) * Qq + (size_t)colblk * NB;
    for (int i = tid; i < 4096; i += 256) {
        int grow = bx * 64 + (i >> 6);
        S[i >> 6][i & 63] = (grow <= Qq) ? __ldcg(&base[(size_t)(i >> 6) * Qq + (i & 63)]) : 0.0f;
    }
}
__device__ __forceinline__ void store_tile(float (*S)[65], int bx, int colblk) {
    int tid = threadIdx.x;
    float* base = g_A + (size_t)(bx * 64) * Qq + (size_t)colblk * NB;
    for (int i = tid; i < 4096; i += 256) {
        int grow = bx * 64 + (i >> 6);
        if (grow <= Qq) base[(size_t)(i >> 6) * Qq + (i & 63)] = S[i >> 6][i & 63];
    }
}
// RMW: global tile (bx,byc) -= acc
__device__ __forceinline__ void rmw_tile(int bx, int byc, float acc[4][4]) {
    int ty = threadIdx.x >> 4, tx = threadIdx.x & 15;
    float* C = g_A + (size_t)(bx * 64 + ty * 4) * Qq + (size_t)byc * 64 + tx * 4;
#pragma unroll
    for (int i = 0; i < 4; i++) {
        if (bx * 64 + ty * 4 + i <= Qq) {
#pragma unroll
            for (int jj = 0; jj < 4; jj++)
                C[(size_t)i * Qq + jj] = __ldcg(&C[(size_t)i * Qq + jj]) - acc[i][jj];
        }
    }
}

// ---------------- kernel 1: per-element transform + scalar sums ----------------
__global__ void k_pre(const float* __restrict__ yt, const float* __restrict__ yp,
                      const float* __restrict__ se, const float* __restrict__ sb) {
    __shared__ double sbuf[1024];
    int tid = threadIdx.x;
    float e = se[0], b = sb[0];
    float sig2 = e + b;
    float inv = 1.0f / ((float)CC * sqrtf(sig2));
    double sy = 0.0, sen = 0.0, sz2 = 0.0;
    for (int i = tid; i < Nn; i += 1024) {
        float y  = (yt[i] - yp[i]) * inv + (float)EULERC;
        float en = expf(-y);
        float u  = expf(-en);
        u = fminf(fmaxf(u, 1e-6f), 1.0f - 1e-6f);
        float zs = 1.41421356237309515f * erfinvf(2.0f * u - 1.0f);
        g_zs[i] = zs;
        sy  += (double)y;
        sen += (double)en;
        sz2 += (double)zs * (double)zs;
    }
    double r;
    r = block_reduce_d(sy, sbuf);  if (tid == 0) g_sums[0] = r;
    r = block_reduce_d(sen, sbuf); if (tid == 0) g_sums[1] = r;
    r = block_reduce_d(sz2, sbuf); if (tid == 0) g_sums[2] = r;
}

// ---------------- kernel 2: histogram + flag reset ----------------
__global__ void k_acc(const long long* __restrict__ Z) {
    int tid = threadIdx.x;                             // 1024
    for (int q = tid; q < Qq; q += 1024) { g_cnt[q] = 0; g_tsum[q] = 0ULL; }
    for (int i = tid; i < (NP + 1) * NP; i += 1024) g_gen[i] = 0;
    if (tid <= NP) g_ftr[tid] = 0;
    if (tid == 0) g_fL = 0;
    __syncthreads();
    for (int i = tid; i < Nn; i += 1024) {
        int q = ((int)Z[i]) & (Qq - 1);
        long long fx = (long long)llrintf(g_zs[i] * ZSCALE);
        atomicAdd(&g_cnt[q], 1);
        atomicAdd(&g_tsum[q], (unsigned long long)fx);
    }
    __syncthreads();
    for (int q = tid; q < Qq; q += 1024) {
        int c = g_cnt[q];
        float t = (float)((double)(long long)g_tsum[q] / (double)ZSCALE);
        g_t[q] = t;
        g_x[q] = (c > 0) ? (t / (float)c) : 0.0f;
    }
}

// ---------------- kernel 3: build A, plus rhs row Qq ----------
__global__ void k_buildA(const float* __restrict__ dist, const float* __restrict__ se,
                         const float* __restrict__ sb, const float* __restrict__ ell) {
    int idx = blockIdx.x * blockDim.x + threadIdx.x;
    if (idx >= (Qq + 1) * Qq) return;
    int q = idx >> 11;
    int r = idx & (Qq - 1);
    if (q == Qq) { g_A[idx] = g_x[r]; return; }
    float e = se[0], b = sb[0];
    float inv2l = -1.0f / (2.0f * ell[0]);
    float scale = b / e;
    int mq = (g_cnt[q] > 0);
    int mr = (g_cnt[r] > 0);
    float v = 0.0f;
    if (mq && mr) v = scale * expf(dist[(size_t)q * LDIM + r] * inv2l);
    if (q == r)  v = mq ? (v + 1.0f / (float)g_cnt[q]) : 1.0f;
    g_A[idx] = v;
}

// ---------------- persistent dataflow Cholesky + forward solve + final ----------
// Block 0 owns the self-feeding critical chain J1..J5; workers take the rest.
__global__ void __launch_bounds__(256, 2) k_chol(const float* __restrict__ se,
                                                 const float* __restrict__ sb,
                                                 float* __restrict__ out) {
    __shared__ float sh[12736];
    float (*PL)[65]   = reinterpret_cast<float(*)[65]>(sh);           // 64x65: L / diag
    float (*Pb)[65]   = reinterpret_cast<float(*)[65]>(sh + 4160);    // 64x65: X1
    float (*Pc)[65]   = reinterpret_cast<float(*)[65]>(sh + 8320);    // 64x65: X2
    float (*buf2)[64] = reinterpret_cast<float(*)[64]>(sh + 12480);   // 2x64 potf2 bcast
    float* ds  = sh + 12608;                                          // 64
    float* rdv = sh + 12672;                                          // 64 (1/diag, survives potf2)
    int tid = threadIdx.x;
    int bid = blockIdx.x;

    if (bid == 0) {
        // ================= critical-chain block =================
        load_tile(PL, 0, 0);
        __syncthreads();
        potf2_core(PL, buf2, ds, g_A, 0);            // PL = L(0)
        publish(&g_fL, 1);

        for (int kb = 0; kb < NP; kb++) {
            int nt0 = kb + 1;
            if (tid < 64) rdv[tid] = __frcp_rn(PL[tid][tid]);
            __syncthreads();

            // ---- J1: trsm tile nt0 (wait: self J4 of kb-1) ----
            wait_eq(&g_gen[nt0 * NP + kb], kb, 32);
            load_tile(Pb, nt0, kb);
            __syncthreads();
            trsm64(PL, Pb, rdv);
            __syncthreads();
            store_tile(Pb, nt0, kb);
            publish(&g_ftr[nt0], kb + 1);

            // ---- J2: trsm tile nt0+1 (wait: worker pair (nt0+1,kb) of kb-1, slack) ----
            if (nt0 + 1 <= NP) {
                wait_eq(&g_gen[(nt0 + 1) * NP + kb], kb, 32);
                load_tile(Pc, nt0 + 1, kb);
                __syncthreads();
                trsm64(PL, Pc, rdv);
                __syncthreads();
                store_tile(Pc, nt0 + 1, kb);
                publish(&g_ftr[nt0 + 1], kb + 1);
            }

            // ---- J3: diag (nt0,nt0) -= Pb Pb^T; potf2 -> L(nt0) (wait: self J5 of kb-1) ----
            if (nt0 <= NP - 1) {
                wait_eq(&g_gen[nt0 * NP + nt0], kb, 32);
                load_tile(PL, nt0, nt0);
                __syncthreads();
                float acc[4][4];
                syrk_acc(Pb, Pb, acc);
                int ty = tid >> 4, tx = tid & 15;
#pragma unroll
                for (int i = 0; i < 4; i++)
#pragma unroll
                    for (int j = 0; j < 4; j++)
                        PL[ty * 4 + i][tx * 4 + j] -= acc[i][j];
                __syncthreads();
                potf2_core(PL, buf2, ds,
                           g_A + (size_t)(nt0 * NB) * Qq + nt0 * NB, nt0);
                publish(&g_fL, nt0 + 1);
            }

            // ---- J4: tile (nt0+1,nt0) -= Pc Pb^T (feeds next J1) ----
            if (nt0 + 1 <= NP) {
                wait_eq(&g_gen[(nt0 + 1) * NP + nt0], kb, 32);
                float acc[4][4];
                syrk_acc(Pc, Pb, acc);
                rmw_tile(nt0 + 1, nt0, acc);
                publish(&g_gen[(nt0 + 1) * NP + nt0], kb + 1);
            }

            // ---- J5: diag (nt0+1,nt0+1) -= Pc Pc^T (feeds next J3) ----
            if (nt0 + 1 <= NP - 1) {
                wait_eq(&g_gen[(nt0 + 1) * NP + (nt0 + 1)], kb, 32);
                float acc[4][4];
                syrk_acc(Pc, Pc, acc);
                rmw_tile(nt0 + 1, nt0 + 1, acc);
                publish(&g_gen[(nt0 + 1) * NP + (nt0 + 1)], kb + 1);
            }
        }

        // ================= final reduction =================
        double* sbuf = reinterpret_cast<double*>(sh);
        double sy2 = 0.0, st2n = 0.0, slogn = 0.0;
        const float* yrow = g_A + (size_t)Qq * Qq;
        for (int q = tid; q < Qq; q += 256) {
            float y = __ldcg(&yrow[q]);
            sy2 += (double)y * (double)y;
            int c = g_cnt[q];
            if (c > 0) {
                double tq = (double)g_t[q];
                st2n  += tq * tq / (double)c;
                slogn += log((double)c);
            }
        }
        double SY2 = block_reduce_d(sy2, sbuf);
        double ST  = block_reduce_d(st2n, sbuf);
        double SL  = block_reduce_d(slogn, sbuf);
        if (tid == 0) {
            double sumlogL = 0.0;
            for (int i = 0; i < NP; i++) sumlogL += g_logdiag[i];
            double e = (double)se[0], b = (double)sb[0];
            double sig2 = e + b;
            double sy = g_sums[0], sen = g_sums[1], sz2 = g_sums[2];
            double S1 = ST - SY2;
            double mld = 2.0 * sy + 2.0 * sen + (double)Nn * log(sig2) + (double)Nn * log(C2C);
            double quad = sig2 / e * (sz2 - S1);
            double logdetR = (double)Nn * log(e) + SL + 2.0 * sumlogL - (double)Nn * log(sig2);
            out[0] = (float)(mld + quad - sz2 + logdetR);
        }
        return;
    }

    // ================= worker blocks =================
    int w = bid - 1;
    int W = gridDim.x - 1;
    for (int kb = 0; kb < NP; kb++) {
        int nt0 = kb + 1;
        int R = NP - kb;                    // #by values (nt0..NP)
        int T = R * (R + 1) / 2;            // all pairs incl. (NP,NP)
        int ntrw = NP - nt0 - 1;            // trsm tiles nt0+2..NP
        if (ntrw < 0) ntrw = 0;
        int njobs = ntrw + T;
        for (int job = w; job < njobs; job += W) {
            if (job < ntrw) {
                // ---- trsm of tile bx against L(kb) ----
                int bx = nt0 + 2 + job;
                wait_ge(&g_fL, kb + 1, 256);
                const float* Lk = g_A + (size_t)(kb * NB) * Qq + kb * NB;
                for (int i = tid; i < 4096; i += 256)
                    PL[i >> 6][i & 63] = __ldcg(&Lk[(size_t)(i >> 6) * Qq + (i & 63)]);
                __syncthreads();
                if (tid < 64) rdv[tid] = __frcp_rn(PL[tid][tid]);
                wait_eq(&g_gen[bx * NP + kb], kb, 256);
                load_tile(Pb, bx, kb);
                __syncthreads();
                trsm64(PL, Pb, rdv);
                __syncthreads();
                store_tile(Pb, bx, kb);
                publish(&g_ftr[bx], kb + 1);
            } else {
                int pj = job - ntrw;
                // skip block-0-owned pairs and nonexistent (NP,NP)
                if (pj == 0 || pj == T - 1) continue;
                if (R >= 2 && (pj == 1 || pj == R)) continue;
                int t2 = pj, by = nt0, len = R;
                while (t2 >= len) { t2 -= len; by++; len--; }
                int bx = by + t2;
                wait_ge(&g_ftr[bx], kb + 1, 256);
                wait_ge(&g_ftr[by], kb + 1, 256);
                wait_eq(&g_gen[bx * NP + by], kb, 256);
                load_tile(PL, bx, kb);
                load_tile(Pb, by, kb);
                __syncthreads();
                float acc[4][4];
                syrk_acc(PL, Pb, acc);
                rmw_tile(bx, by, acc);
                publish(&g_gen[bx * NP + by], kb + 1);
            }
        }
    }
}

// ---------------- launch ----------------
extern "C" void kernel_launch(void* const* d_in, const int* in_sizes, int n_in,
                              void* d_out, int out_size) {
    const float*     y_true = (const float*)d_in[0];
    const float*     y_pred = (const float*)d_in[1];
    const float*     sig2e  = (const float*)d_in[2];
    const float*     sig2bs = (const float*)d_in[3];
    const float*     ell    = (const float*)d_in[4];
    const float*     dist   = (const float*)d_in[5];
    const long long* Z_idx  = (const long long*)d_in[6];
    float* out = (float*)d_out;

    int nsm = 0;
    cudaDeviceGetAttribute(&nsm, cudaDevAttrMultiProcessorCount, 0);
    if (nsm <= 0) nsm = 148;
    int nblocks = 2 * nsm;   // co-resident via __launch_bounds__(256,2)

    k_pre<<<1, 1024>>>(y_true, y_pred, sig2e, sig2bs);
    k_acc<<<1, 1024>>>(Z_idx);
    int nbuild = ((Qq + 1) * Qq + 1023) / 1024;
    k_buildA<<<nbuild, 1024>>>(dist, sig2e, sig2bs, ell);

    k_chol<<<nblocks, 256>>>(sig2e, sig2bs, out);
}

// round 10
// speedup vs baseline: 1.0705x; 1.0705x over previous
#include <cuda_runtime.h>
#include <math.h>

// Problem constants
#define Nn   4096
#define Qq   2048
#define LDIM 8192
#define NB   64
#define NP   (Qq/NB)   // 32

#define EULERC 0.5772156649015329
#define CC     0.7796968012336761   // sqrt(6)/pi
#define C2C    0.6079271018540267   // 6/pi^2
#define ZSCALE 16777216.0f          // 2^24 fixed-point scale for deterministic sums
#define FP    32                    // flag padding: 32 ints = 128 B per flag

// ---------------- device scratch (static, allocation-free) ----------------
__device__ float  g_zs[Nn];
__device__ double g_sums[3];
__device__ int    g_cnt[Qq];
__device__ unsigned long long g_tsum[Qq];
__device__ float  g_t[Qq];
__device__ float  g_x[Qq];
// (Qq+1) rows x Qq cols: row Qq holds the rhs r, becomes y = L^{-1} r after sweep
__device__ float  g_A[(size_t)(Qq + 1) * Qq];
__device__ double g_logdiag[NP];
// dataflow flags, one per 128-B cache line
__device__ int    g_fL[FP];                      // L(s) published <=> >= s+1
__device__ int    g_ftr[(NP + 1) * FP];          // trsm of tile bx done for col kb <=> >= kb+1
__device__ int    g_gen[(NP + 1) * NP * FP];     // #syrk updates applied to tile (bx,by)

// ---------------- helpers ----------------
__device__ __forceinline__ double block_reduce_d(double v, double* sbuf) {
    int t = threadIdx.x;
    sbuf[t] = v;
    __syncthreads();
    for (int s = blockDim.x >> 1; s > 0; s >>= 1) {
        if (t < s) sbuf[t] += sbuf[t + s];
        __syncthreads();
    }
    double r = sbuf[0];
    __syncthreads();
    return r;
}

// polls are plain L2 loads (no RMW); publishes are atomicExch.
__device__ __forceinline__ void wait_eq(int* p, int v, int ns0, int nsmax) {
    if (threadIdx.x == 0) {
        int ns = ns0;
        while (__ldcg((const int*)p) != v) {
            __nanosleep(ns);
            ns = (ns < nsmax) ? (ns << 1) : nsmax;
        }
        __threadfence();
    }
    __syncthreads();
}
__device__ __forceinline__ void wait_ge(int* p, int v, int ns0, int nsmax) {
    if (threadIdx.x == 0) {
        int ns = ns0;
        while (__ldcg((const int*)p) < v) {
            __nanosleep(ns);
            ns = (ns < nsmax) ? (ns << 1) : nsmax;
        }
        __threadfence();
    }
    __syncthreads();
}
__device__ __forceinline__ void publish(int* p, int v) {
    __threadfence();
    __syncthreads();
    if (threadIdx.x == 0) atomicExch(p, v);
}

// 64x64 Cholesky of tile in shared S; L written to gout (ld=Qq; upper triangle
// garbage by design) AND back into S. Raw-column variant.
__device__ void potf2_core(float S[64][65], float buf[2][64], float* ds,
                           float* gout, int logidx) {
    int t = threadIdx.x;
    int tcol = t & 63;
    int rbase = (t >> 6) * 16;
    float c[16];
#pragma unroll
    for (int i = 0; i < 16; i++) c[i] = S[rbase + i][tcol];
    if (tcol == 0) {
#pragma unroll
        for (int i = 0; i < 16; i++) buf[0][rbase + i] = c[i];
    }
    __syncthreads();
    for (int j = 0; j < 64; j++) {
        float* bc = buf[j & 1];
        if (t == 0) ds[j] = bc[j];
        if (tcol > j) {
            float fr = bc[tcol] * __frcp_rn(bc[j]);
#pragma unroll
            for (int i = 0; i < 16; i++) c[i] -= fr * bc[rbase + i];
            if (tcol == j + 1) {
#pragma unroll
                for (int i = 0; i < 16; i++) buf[(j + 1) & 1][rbase + i] = c[i];
            }
        }
        __syncthreads();
    }
    float r = rsqrtf(ds[tcol]);
#pragma unroll
    for (int i = 0; i < 16; i++) {
        float v = c[i] * r;
        gout[(size_t)(rbase + i) * Qq + tcol] = v;
        S[rbase + i][tcol] = v;
    }
    if (t < 64) {
        float lg = logf(ds[tcol]);
#pragma unroll
        for (int off = 16; off > 0; off >>= 1)
            lg += __shfl_down_sync(0xffffffffu, lg, off);
        if ((t & 31) == 0) buf[1][t >> 5] = lg;
    }
    __syncthreads();
    if (t == 0)
        g_logdiag[logidx] = 0.5 * ((double)buf[1][0] + (double)buf[1][1]);
    __syncthreads();
}

// forward substitution of 64 rows in X against lower-tri Ld (rd = 1/diag)
__device__ __forceinline__ void trsm64(float (*Ld)[65], float (*X)[65],
                                       const float* rd) {
    int tid = threadIdx.x;
    if (tid < 64) {
        float x[64];
#pragma unroll
        for (int c = 0; c < 64; c++) x[c] = X[tid][c];
#pragma unroll
        for (int c = 0; c < 64; c++) {
            float a0 = 0.f, a1 = 0.f, a2 = 0.f, a3 = 0.f;
#pragma unroll
            for (int p = 0; p < c; p += 4) {
                a0 += x[p] * Ld[c][p];
                if (p + 1 < c) a1 += x[p + 1] * Ld[c][p + 1];
                if (p + 2 < c) a2 += x[p + 2] * Ld[c][p + 2];
                if (p + 3 < c) a3 += x[p + 3] * Ld[c][p + 3];
            }
            x[c] = (x[c] - ((a0 + a1) + (a2 + a3))) * rd[c];
        }
#pragma unroll
        for (int c = 0; c < 64; c++) X[tid][c] = x[c];
    }
}

// 64x64x64 A*B^T accumulate: acc[4][4] per thread (16x16 grid of threads)
__device__ __forceinline__ void syrk_acc(float (*Pa)[65], float (*Pb)[65],
                                         float acc[4][4]) {
    int ty = threadIdx.x >> 4, tx = threadIdx.x & 15;
#pragma unroll
    for (int i = 0; i < 4; i++)
#pragma unroll
        for (int j = 0; j < 4; j++) acc[i][j] = 0.0f;
#pragma unroll 8
    for (int k = 0; k < 64; k++) {
        float a0 = Pa[ty * 4 + 0][k], a1 = Pa[ty * 4 + 1][k];
        float a2 = Pa[ty * 4 + 2][k], a3 = Pa[ty * 4 + 3][k];
        float b0 = Pb[tx * 4 + 0][k], b1 = Pb[tx * 4 + 1][k];
        float b2 = Pb[tx * 4 + 2][k], b3 = Pb[tx * 4 + 3][k];
        acc[0][0] += a0 * b0; acc[0][1] += a0 * b1; acc[0][2] += a0 * b2; acc[0][3] += a0 * b3;
        acc[1][0] += a1 * b0; acc[1][1] += a1 * b1; acc[1][2] += a1 * b2; acc[1][3] += a1 * b3;
        acc[2][0] += a2 * b0; acc[2][1] += a2 * b1; acc[2][2] += a2 * b2; acc[2][3] += a2 * b3;
        acc[3][0] += a3 * b0; acc[3][1] += a3 * b1; acc[3][2] += a3 * b2; acc[3][3] += a3 * b3;
    }
}

// load/store 64x64 tile (row-guarded vs Qq+1 rows)
__device__ __forceinline__ void load_tile(float (*S)[65], int bx, int colblk) {
    int tid = threadIdx.x;
    const float* base = g_A + (size_t)(bx * 64) * Qq + (size_t)colblk * NB;
    for (int i = tid; i < 4096; i += 256) {
        int grow = bx * 64 + (i >> 6);
        S[i >> 6][i & 63] = (grow <= Qq) ? __ldcg(&base[(size_t)(i >> 6) * Qq + (i & 63)]) : 0.0f;
    }
}
__device__ __forceinline__ void store_tile(float (*S)[65], int bx, int colblk) {
    int tid = threadIdx.x;
    float* base = g_A + (size_t)(bx * 64) * Qq + (size_t)colblk * NB;
    for (int i = tid; i < 4096; i += 256) {
        int grow = bx * 64 + (i >> 6);
        if (grow <= Qq) base[(size_t)(i >> 6) * Qq + (i & 63)] = S[i >> 6][i & 63];
    }
}
// RMW: global tile (bx,byc) -= acc
__device__ __forceinline__ void rmw_tile(int bx, int byc, float acc[4][4]) {
    int ty = threadIdx.x >> 4, tx = threadIdx.x & 15;
    float* C = g_A + (size_t)(bx * 64 + ty * 4) * Qq + (size_t)byc * 64 + tx * 4;
#pragma unroll
    for (int i = 0; i < 4; i++) {
        if (bx * 64 + ty * 4 + i <= Qq) {
#pragma unroll
            for (int jj = 0; jj < 4; jj++)
                C[(size_t)i * Qq + jj] = __ldcg(&C[(size_t)i * Qq + jj]) - acc[i][jj];
        }
    }
}

// ---------------- kernel 1: per-element transform + scalar sums ----------------
__global__ void k_pre(const float* __restrict__ yt, const float* __restrict__ yp,
                      const float* __restrict__ se, const float* __restrict__ sb) {
    __shared__ double sbuf[1024];
    int tid = threadIdx.x;
    float e = se[0], b = sb[0];
    float sig2 = e + b;
    float inv = 1.0f / ((float)CC * sqrtf(sig2));
    double sy = 0.0, sen = 0.0, sz2 = 0.0;
    for (int i = tid; i < Nn; i += 1024) {
        float y  = (yt[i] - yp[i]) * inv + (float)EULERC;
        float en = expf(-y);
        float u  = expf(-en);
        u = fminf(fmaxf(u, 1e-6f), 1.0f - 1e-6f);
        float zs = 1.41421356237309515f * erfinvf(2.0f * u - 1.0f);
        g_zs[i] = zs;
        sy  += (double)y;
        sen += (double)en;
        sz2 += (double)zs * (double)zs;
    }
    double r;
    r = block_reduce_d(sy, sbuf);  if (tid == 0) g_sums[0] = r;
    r = block_reduce_d(sen, sbuf); if (tid == 0) g_sums[1] = r;
    r = block_reduce_d(sz2, sbuf); if (tid == 0) g_sums[2] = r;
}

// ---------------- kernel 2: histogram + flag reset ----------------
__global__ void k_acc(const long long* __restrict__ Z) {
    int tid = threadIdx.x;                             // 1024
    for (int q = tid; q < Qq; q += 1024) { g_cnt[q] = 0; g_tsum[q] = 0ULL; }
    for (int i = tid; i < (NP + 1) * NP * FP; i += 1024) g_gen[i] = 0;
    for (int i = tid; i < (NP + 1) * FP; i += 1024) g_ftr[i] = 0;
    if (tid < FP) g_fL[tid] = 0;
    __syncthreads();
    for (int i = tid; i < Nn; i += 1024) {
        int q = ((int)Z[i]) & (Qq - 1);
        long long fx = (long long)llrintf(g_zs[i] * ZSCALE);
        atomicAdd(&g_cnt[q], 1);
        atomicAdd(&g_tsum[q], (unsigned long long)fx);
    }
    __syncthreads();
    for (int q = tid; q < Qq; q += 1024) {
        int c = g_cnt[q];
        float t = (float)((double)(long long)g_tsum[q] / (double)ZSCALE);
        g_t[q] = t;
        g_x[q] = (c > 0) ? (t / (float)c) : 0.0f;
    }
}

// ---------------- kernel 3: build A, plus rhs row Qq ----------
__global__ void k_buildA(const float* __restrict__ dist, const float* __restrict__ se,
                         const float* __restrict__ sb, const float* __restrict__ ell) {
    int idx = blockIdx.x * blockDim.x + threadIdx.x;
    if (idx >= (Qq + 1) * Qq) return;
    int q = idx >> 11;
    int r = idx & (Qq - 1);
    if (q == Qq) { g_A[idx] = g_x[r]; return; }
    float e = se[0], b = sb[0];
    float inv2l = -1.0f / (2.0f * ell[0]);
    float scale = b / e;
    int mq = (g_cnt[q] > 0);
    int mr = (g_cnt[r] > 0);
    float v = 0.0f;
    if (mq && mr) v = scale * expf(dist[(size_t)q * LDIM + r] * inv2l);
    if (q == r)  v = mq ? (v + 1.0f / (float)g_cnt[q]) : 1.0f;
    g_A[idx] = v;
}

// ---------------- persistent dataflow Cholesky + forward solve + final ----------
// Block 0 owns the critical chain J1..J4 (round-7 structure); workers the rest.
__global__ void __launch_bounds__(256, 2) k_chol(const float* __restrict__ se,
                                                 const float* __restrict__ sb,
                                                 float* __restrict__ out) {
    __shared__ float sh[12672];
    float (*Pa)[65]   = reinterpret_cast<float(*)[65]>(sh);           // 64x65
    float (*Pb)[65]   = reinterpret_cast<float(*)[65]>(sh + 4160);    // 64x65
    float (*Pc)[65]   = reinterpret_cast<float(*)[65]>(sh + 8320);    // 64x65
    float (*buf2)[64] = reinterpret_cast<float(*)[64]>(sh + 12480);   // 2x64
    float* ds = sh + 12608;                                           // 64
    int tid = threadIdx.x;
    int bid = blockIdx.x;

    if (bid == 0) {
        // ================= critical-chain block =================
        load_tile(Pa, 0, 0);
        __syncthreads();
        potf2_core(Pa, buf2, ds, g_A, 0);            // Pa = L(0)
        publish(g_fL, 1);

        for (int kb = 0; kb < NP; kb++) {
            int nt0 = kb + 1;
            if (tid < 64) buf2[0][tid] = __frcp_rn(Pa[tid][tid]);
            __syncthreads();

            // ---- J1: trsm tile nt0 ----
            wait_eq(&g_gen[(nt0 * NP + kb) * FP], kb, 32, 32);
            load_tile(Pb, nt0, kb);
            __syncthreads();
            trsm64(Pa, Pb, buf2[0]);
            __syncthreads();
            store_tile(Pb, nt0, kb);
            publish(&g_ftr[nt0 * FP], kb + 1);

            // ---- J2: trsm tile nt0+1 ----
            if (nt0 + 1 <= NP) {
                wait_eq(&g_gen[((nt0 + 1) * NP + kb) * FP], kb, 32, 32);
                load_tile(Pc, nt0 + 1, kb);
                __syncthreads();
                trsm64(Pa, Pc, buf2[0]);
                __syncthreads();
                store_tile(Pc, nt0 + 1, kb);
                publish(&g_ftr[(nt0 + 1) * FP], kb + 1);
            }

            // ---- J3: diag (nt0,nt0) -= X1 X1^T; potf2 -> L(nt0) in Pa ----
            if (nt0 <= NP - 1) {
                wait_eq(&g_gen[(nt0 * NP + nt0) * FP], kb, 32, 32);
                load_tile(Pa, nt0, nt0);
                __syncthreads();
                float acc[4][4];
                syrk_acc(Pb, Pb, acc);
                int ty = tid >> 4, tx = tid & 15;
#pragma unroll
                for (int i = 0; i < 4; i++)
#pragma unroll
                    for (int j = 0; j < 4; j++)
                        Pa[ty * 4 + i][tx * 4 + j] -= acc[i][j];
                __syncthreads();
                potf2_core(Pa, buf2, ds,
                           g_A + (size_t)(nt0 * NB) * Qq + nt0 * NB, nt0);
                publish(g_fL, nt0 + 1);
            }

            // ---- J4: tile (nt0+1, nt0) -= X2 X1^T (RMW global) ----
            if (nt0 + 1 <= NP) {
                wait_eq(&g_gen[((nt0 + 1) * NP + nt0) * FP], kb, 32, 32);
                float acc[4][4];
                syrk_acc(Pc, Pb, acc);
                rmw_tile(nt0 + 1, nt0, acc);
                publish(&g_gen[((nt0 + 1) * NP + nt0) * FP], kb + 1);
            }
        }

        // ================= final reduction =================
        double* sbuf = reinterpret_cast<double*>(sh);
        double sy2 = 0.0, st2n = 0.0, slogn = 0.0;
        const float* yrow = g_A + (size_t)Qq * Qq;
        for (int q = tid; q < Qq; q += 256) {
            float y = __ldcg(&yrow[q]);
            sy2 += (double)y * (double)y;
            int c = g_cnt[q];
            if (c > 0) {
                double tq = (double)g_t[q];
                st2n  += tq * tq / (double)c;
                slogn += log((double)c);
            }
        }
        double SY2 = block_reduce_d(sy2, sbuf);
        double ST  = block_reduce_d(st2n, sbuf);
        double SL  = block_reduce_d(slogn, sbuf);
        if (tid == 0) {
            double sumlogL = 0.0;
            for (int i = 0; i < NP; i++) sumlogL += g_logdiag[i];
            double e = (double)se[0], b = (double)sb[0];
            double sig2 = e + b;
            double sy = g_sums[0], sen = g_sums[1], sz2 = g_sums[2];
            double S1 = ST - SY2;
            double mld = 2.0 * sy + 2.0 * sen + (double)Nn * log(sig2) + (double)Nn * log(C2C);
            double quad = sig2 / e * (sz2 - S1);
            double logdetR = (double)Nn * log(e) + SL + 2.0 * sumlogL - (double)Nn * log(sig2);
            out[0] = (float)(mld + quad - sz2 + logdetR);
        }
        return;
    }

    // ================= worker blocks =================
    int w = bid - 1;
    int W = gridDim.x - 1;
    for (int kb = 0; kb < NP; kb++) {
        int nt0 = kb + 1;
        int m = NP - 1 - kb;
        if (m < 1) continue;
        int T = (m + 1) * (m + 2) / 2;     // full pair triangle incl. (NP,NP)
        int ntrw = m - 1;                  // trsm tiles nt0+2 .. NP
        int nsyw = (T - 3 > 0) ? (T - 3) : 0;  // exclude (nt0,nt0), (nt0+1,nt0), (NP,NP)
        int njobs = ntrw + nsyw;
        for (int job = w; job < njobs; job += W) {
            if (job < ntrw) {
                // ---- trsm of tile bx against L(kb) ----
                int bx = nt0 + 2 + job;
                wait_ge(g_fL, kb + 1, 128, 4096);
                const float* Lk = g_A + (size_t)(kb * NB) * Qq + kb * NB;
                for (int i = tid; i < 4096; i += 256)
                    Pa[i >> 6][i & 63] = __ldcg(&Lk[(size_t)(i >> 6) * Qq + (i & 63)]);
                __syncthreads();
                if (tid < 64) buf2[0][tid] = __frcp_rn(Pa[tid][tid]);
                wait_eq(&g_gen[(bx * NP + kb) * FP], kb, 128, 4096);
                load_tile(Pb, bx, kb);
                __syncthreads();
                trsm64(Pa, Pb, buf2[0]);
                __syncthreads();
                store_tile(Pb, bx, kb);
                publish(&g_ftr[bx * FP], kb + 1);
            } else {
                // ---- regular syrk tile: pair index pj in by-major order ----
                int pj = 2 + (job - ntrw);
                int t2 = pj, by = nt0, len = m + 1;
                while (t2 >= len) { t2 -= len; by++; len--; }
                int bx = by + t2;
                wait_ge(&g_ftr[bx * FP], kb + 1, 128, 4096);
                wait_ge(&g_ftr[by * FP], kb + 1, 128, 4096);
                wait_eq(&g_gen[(bx * NP + by) * FP], kb, 128, 4096);
                load_tile(Pa, bx, kb);
                load_tile(Pb, by, kb);
                __syncthreads();
                float acc[4][4];
                syrk_acc(Pa, Pb, acc);
                rmw_tile(bx, by, acc);
                publish(&g_gen[(bx * NP + by) * FP], kb + 1);
            }
        }
    }
}

// ---------------- launch ----------------
extern "C" void kernel_launch(void* const* d_in, const int* in_sizes, int n_in,
                              void* d_out, int out_size) {
    const float*     y_true = (const float*)d_in[0];
    const float*     y_pred = (const float*)d_in[1];
    const float*     sig2e  = (const float*)d_in[2];
    const float*     sig2bs = (const float*)d_in[3];
    const float*     ell    = (const float*)d_in[4];
    const float*     dist   = (const float*)d_in[5];
    const long long* Z_idx  = (const long long*)d_in[6];
    float* out = (float*)d_out;

    int nsm = 0;
    cudaDeviceGetAttribute(&nsm, cudaDevAttrMultiProcessorCount, 0);
    if (nsm <= 0) nsm = 148;
    int nblocks = 2 * nsm;   // co-resident via __launch_bounds__(256,2)

    k_pre<<<1, 1024>>>(y_true, y_pred, sig2e, sig2bs);
    k_acc<<<1, 1024>>>(Z_idx);
    int nbuild = ((Qq + 1) * Qq + 1023) / 1024;
    k_buildA<<<nbuild, 1024>>>(dist, sig2e, sig2bs, ell);

    k_chol<<<nblocks, 256>>>(sig2e, sig2bs, out);
}

// round 11
// speedup vs baseline: 1.8799x; 1.7561x over previous
#include <cuda_runtime.h>
#include <math.h>

// Problem constants
#define Nn   4096
#define Qq   2048
#define LDIM 8192
#define NB   64
#define NP   (Qq/NB)   // 32

#define EULERC 0.5772156649015329
#define CC     0.7796968012336761   // sqrt(6)/pi
#define C2C    0.6079271018540267   // 6/pi^2
#define ZSCALE 16777216.0f          // 2^24 fixed-point scale for deterministic sums
#define FP    32                    // flag padding: 32 ints = 128 B per flag

// ---------------- device scratch (static, allocation-free) ----------------
__device__ float  g_zs[Nn];
__device__ double g_sums[3];
__device__ int    g_cnt[Qq];
__device__ unsigned long long g_tsum[Qq];
__device__ float  g_t[Qq];
__device__ float  g_x[Qq];
// (Qq+1) rows x Qq cols: row Qq holds the rhs r, becomes y = L^{-1} r after sweep
__device__ float  g_A[(size_t)(Qq + 1) * Qq];
__device__ double g_logdiag[NP];
// dataflow flags, one per 128-B cache line
__device__ int    g_fL[FP];                      // L(s) published <=> >= s+1
__device__ int    g_ftr[(NP + 1) * FP];          // trsm of tile bx done for col kb <=> >= kb+1
__device__ int    g_gen[(NP + 1) * NP * FP];     // #syrk updates applied to tile (bx,by)

// ---------------- helpers ----------------
__device__ __forceinline__ double block_reduce_d(double v, double* sbuf) {
    int t = threadIdx.x;
    sbuf[t] = v;
    __syncthreads();
    for (int s = blockDim.x >> 1; s > 0; s >>= 1) {
        if (t < s) sbuf[t] += sbuf[t + s];
        __syncthreads();
    }
    double r = sbuf[0];
    __syncthreads();
    return r;
}

// polls are plain L2 loads (no RMW); publishes are atomicExch.
__device__ __forceinline__ void wait_eq(int* p, int v, int ns) {
    if (threadIdx.x == 0) {
        while (__ldcg((const int*)p) != v) __nanosleep(ns);
        __threadfence();
    }
    __syncthreads();
}
__device__ __forceinline__ void wait_ge(int* p, int v, int ns) {
    if (threadIdx.x == 0) {
        while (__ldcg((const int*)p) < v) __nanosleep(ns);
        __threadfence();
    }
    __syncthreads();
}
__device__ __forceinline__ void publish(int* p, int v) {
    __threadfence();
    __syncthreads();
    if (threadIdx.x == 0) atomicExch(p, v);
}

// 64x64 Cholesky of tile in shared S; L written to gout (ld=Qq; upper triangle
// garbage by design) AND back into S. Raw-column variant.
__device__ void potf2_core(float S[64][65], float buf[2][64], float* ds,
                           float* gout, int logidx) {
    int t = threadIdx.x;
    int tcol = t & 63;
    int rbase = (t >> 6) * 16;
    float c[16];
#pragma unroll
    for (int i = 0; i < 16; i++) c[i] = S[rbase + i][tcol];
    if (tcol == 0) {
#pragma unroll
        for (int i = 0; i < 16; i++) buf[0][rbase + i] = c[i];
    }
    __syncthreads();
    for (int j = 0; j < 64; j++) {
        float* bc = buf[j & 1];
        if (t == 0) ds[j] = bc[j];
        if (tcol > j) {
            float fr = bc[tcol] * __frcp_rn(bc[j]);
#pragma unroll
            for (int i = 0; i < 16; i++) c[i] -= fr * bc[rbase + i];
            if (tcol == j + 1) {
#pragma unroll
                for (int i = 0; i < 16; i++) buf[(j + 1) & 1][rbase + i] = c[i];
            }
        }
        __syncthreads();
    }
    float r = rsqrtf(ds[tcol]);
#pragma unroll
    for (int i = 0; i < 16; i++) {
        float v = c[i] * r;
        gout[(size_t)(rbase + i) * Qq + tcol] = v;
        S[rbase + i][tcol] = v;
    }
    if (t < 64) {
        float lg = logf(ds[tcol]);
#pragma unroll
        for (int off = 16; off > 0; off >>= 1)
            lg += __shfl_down_sync(0xffffffffu, lg, off);
        if ((t & 31) == 0) buf[1][t >> 5] = lg;
    }
    __syncthreads();
    if (t == 0)
        g_logdiag[logidx] = 0.5 * ((double)buf[1][0] + (double)buf[1][1]);
    __syncthreads();
}

// forward substitution of 64 rows in X against lower-tri Ld (rd = 1/diag)
__device__ __forceinline__ void trsm64(float (*Ld)[65], float (*X)[65],
                                       const float* rd) {
    int tid = threadIdx.x;
    if (tid < 64) {
        float x[64];
#pragma unroll
        for (int c = 0; c < 64; c++) x[c] = X[tid][c];
#pragma unroll
        for (int c = 0; c < 64; c++) {
            float a0 = 0.f, a1 = 0.f, a2 = 0.f, a3 = 0.f;
#pragma unroll
            for (int p = 0; p < c; p += 4) {
                a0 += x[p] * Ld[c][p];
                if (p + 1 < c) a1 += x[p + 1] * Ld[c][p + 1];
                if (p + 2 < c) a2 += x[p + 2] * Ld[c][p + 2];
                if (p + 3 < c) a3 += x[p + 3] * Ld[c][p + 3];
            }
            x[c] = (x[c] - ((a0 + a1) + (a2 + a3))) * rd[c];
        }
#pragma unroll
        for (int c = 0; c < 64; c++) X[tid][c] = x[c];
    }
}

// 64x64x64 A*B^T accumulate: acc[4][4] per thread (16x16 grid of threads)
__device__ __forceinline__ void syrk_acc(float (*Pa)[65], float (*Pb)[65],
                                         float acc[4][4]) {
    int ty = threadIdx.x >> 4, tx = threadIdx.x & 15;
#pragma unroll
    for (int i = 0; i < 4; i++)
#pragma unroll
        for (int j = 0; j < 4; j++) acc[i][j] = 0.0f;
#pragma unroll 8
    for (int k = 0; k < 64; k++) {
        float a0 = Pa[ty * 4 + 0][k], a1 = Pa[ty * 4 + 1][k];
        float a2 = Pa[ty * 4 + 2][k], a3 = Pa[ty * 4 + 3][k];
        float b0 = Pb[tx * 4 + 0][k], b1 = Pb[tx * 4 + 1][k];
        float b2 = Pb[tx * 4 + 2][k], b3 = Pb[tx * 4 + 3][k];
        acc[0][0] += a0 * b0; acc[0][1] += a0 * b1; acc[0][2] += a0 * b2; acc[0][3] += a0 * b3;
        acc[1][0] += a1 * b0; acc[1][1] += a1 * b1; acc[1][2] += a1 * b2; acc[1][3] += a1 * b3;
        acc[2][0] += a2 * b0; acc[2][1] += a2 * b1; acc[2][2] += a2 * b2; acc[2][3] += a2 * b3;
        acc[3][0] += a3 * b0; acc[3][1] += a3 * b1; acc[3][2] += a3 * b2; acc[3][3] += a3 * b3;
    }
}

// load/store 64x64 tile (row-guarded vs Qq+1 rows)
__device__ __forceinline__ void load_tile(float (*S)[65], int bx, int colblk) {
    int tid = threadIdx.x;
    const float* base = g_A + (size_t)(bx * 64) * Qq + (size_t)colblk * NB;
    for (int i = tid; i < 4096; i += 256) {
        int grow = bx * 64 + (i >> 6);
        S[i >> 6][i & 63] = (grow <= Qq) ? __ldcg(&base[(size_t)(i >> 6) * Qq + (i & 63)]) : 0.0f;
    }
}
__device__ __forceinline__ void store_tile(float (*S)[65], int bx, int colblk) {
    int tid = threadIdx.x;
    float* base = g_A + (size_t)(bx * 64) * Qq + (size_t)colblk * NB;
    for (int i = tid; i < 4096; i += 256) {
        int grow = bx * 64 + (i >> 6);
        if (grow <= Qq) base[(size_t)(i >> 6) * Qq + (i & 63)] = S[i >> 6][i & 63];
    }
}
// RMW: global tile (bx,byc) -= acc
__device__ __forceinline__ void rmw_tile(int bx, int byc, float acc[4][4]) {
    int ty = threadIdx.x >> 4, tx = threadIdx.x & 15;
    float* C = g_A + (size_t)(bx * 64 + ty * 4) * Qq + (size_t)byc * 64 + tx * 4;
#pragma unroll
    for (int i = 0; i < 4; i++) {
        if (bx * 64 + ty * 4 + i <= Qq) {
#pragma unroll
            for (int jj = 0; jj < 4; jj++)
                C[(size_t)i * Qq + jj] = __ldcg(&C[(size_t)i * Qq + jj]) - acc[i][jj];
        }
    }
}

// ---------------- kernel 1: per-element transform + scalar sums ----------------
__global__ void k_pre(const float* __restrict__ yt, const float* __restrict__ yp,
                      const float* __restrict__ se, const float* __restrict__ sb) {
    __shared__ double sbuf[1024];
    int tid = threadIdx.x;
    float e = se[0], b = sb[0];
    float sig2 = e + b;
    float inv = 1.0f / ((float)CC * sqrtf(sig2));
    double sy = 0.0, sen = 0.0, sz2 = 0.0;
    for (int i = tid; i < Nn; i += 1024) {
        float y  = (yt[i] - yp[i]) * inv + (float)EULERC;
        float en = expf(-y);
        float u  = expf(-en);
        u = fminf(fmaxf(u, 1e-6f), 1.0f - 1e-6f);
        float zs = 1.41421356237309515f * erfinvf(2.0f * u - 1.0f);
        g_zs[i] = zs;
        sy  += (double)y;
        sen += (double)en;
        sz2 += (double)zs * (double)zs;
    }
    double r;
    r = block_reduce_d(sy, sbuf);  if (tid == 0) g_sums[0] = r;
    r = block_reduce_d(sen, sbuf); if (tid == 0) g_sums[1] = r;
    r = block_reduce_d(sz2, sbuf); if (tid == 0) g_sums[2] = r;
}

// ---------------- kernel 2: histogram + flag reset ----------------
__global__ void k_acc(const long long* __restrict__ Z) {
    int tid = threadIdx.x;                             // 1024
    for (int q = tid; q < Qq; q += 1024) { g_cnt[q] = 0; g_tsum[q] = 0ULL; }
    for (int i = tid; i < (NP + 1) * NP * FP; i += 1024) g_gen[i] = 0;
    for (int i = tid; i < (NP + 1) * FP; i += 1024) g_ftr[i] = 0;
    if (tid < FP) g_fL[tid] = 0;
    __syncthreads();
    for (int i = tid; i < Nn; i += 1024) {
        int q = ((int)Z[i]) & (Qq - 1);
        long long fx = (long long)llrintf(g_zs[i] * ZSCALE);
        atomicAdd(&g_cnt[q], 1);
        atomicAdd(&g_tsum[q], (unsigned long long)fx);
    }
    __syncthreads();
    for (int q = tid; q < Qq; q += 1024) {
        int c = g_cnt[q];
        float t = (float)((double)(long long)g_tsum[q] / (double)ZSCALE);
        g_t[q] = t;
        g_x[q] = (c > 0) ? (t / (float)c) : 0.0f;
    }
}

// ---------------- kernel 3: build A, plus rhs row Qq ----------
__global__ void k_buildA(const float* __restrict__ dist, const float* __restrict__ se,
                         const float* __restrict__ sb, const float* __restrict__ ell) {
    int idx = blockIdx.x * blockDim.x + threadIdx.x;
    if (idx >= (Qq + 1) * Qq) return;
    int q = idx >> 11;
    int r = idx & (Qq - 1);
    if (q == Qq) { g_A[idx] = g_x[r]; return; }
    float e = se[0], b = sb[0];
    float inv2l = -1.0f / (2.0f * ell[0]);
    float scale = b / e;
    int mq = (g_cnt[q] > 0);
    int mr = (g_cnt[r] > 0);
    float v = 0.0f;
    if (mq && mr) v = scale * expf(dist[(size_t)q * LDIM + r] * inv2l);
    if (q == r)  v = mq ? (v + 1.0f / (float)g_cnt[q]) : 1.0f;
    g_A[idx] = v;
}

// ---------------- persistent dataflow Cholesky + forward solve + final ----------
// ROUND-7 STRUCTURE (proven 847us): block 0 owns trsm(nt0) + fused diag potf2
// only; workers take all other trsm and syrk tiles. This round changes ONLY
// the flag mechanics (padded lines, load-polls, short quanta).
__global__ void __launch_bounds__(256, 2) k_chol(const float* __restrict__ se,
                                                 const float* __restrict__ sb,
                                                 float* __restrict__ out) {
    __shared__ float sh[8512];
    float (*Pa)[65]   = reinterpret_cast<float(*)[65]>(sh);          // 64x65
    float (*Pb)[65]   = reinterpret_cast<float(*)[65]>(sh + 4160);   // 64x65
    float (*buf2)[64] = reinterpret_cast<float(*)[64]>(sh + 8320);   // 2x64
    float* ds = sh + 8448;                                           // 64
    int tid = threadIdx.x;
    int bid = blockIdx.x;

    if (bid == 0) {
        // ================= critical-chain block =================
        load_tile(Pa, 0, 0);
        __syncthreads();
        potf2_core(Pa, buf2, ds, g_A, 0);            // Pa = L(0)
        publish(g_fL, 1);

        for (int kb = 0; kb < NP; kb++) {
            int nt0 = kb + 1;
            // rd = 1/diag(L(kb)) (Pa holds L(kb))
            if (tid < 64) buf2[0][tid] = __frcp_rn(Pa[tid][tid]);
            __syncthreads();

            // ---- J1: trsm tile nt0 ----
            wait_eq(&g_gen[(nt0 * NP + kb) * FP], kb, 32);
            load_tile(Pb, nt0, kb);
            __syncthreads();
            trsm64(Pa, Pb, buf2[0]);
            __syncthreads();
            store_tile(Pb, nt0, kb);
            publish(&g_ftr[nt0 * FP], kb + 1);

            // ---- J3: diag (nt0,nt0) -= X1 X1^T; potf2 -> L(nt0) in Pa ----
            if (nt0 <= NP - 1) {
                wait_eq(&g_gen[(nt0 * NP + nt0) * FP], kb, 32);
                load_tile(Pa, nt0, nt0);
                __syncthreads();
                float acc[4][4];
                syrk_acc(Pb, Pb, acc);
                int ty = tid >> 4, tx = tid & 15;
#pragma unroll
                for (int i = 0; i < 4; i++)
#pragma unroll
                    for (int j = 0; j < 4; j++)
                        Pa[ty * 4 + i][tx * 4 + j] -= acc[i][j];
                __syncthreads();
                potf2_core(Pa, buf2, ds,
                           g_A + (size_t)(nt0 * NB) * Qq + nt0 * NB, nt0);
                publish(g_fL, nt0 + 1);
            }
        }

        // ================= final reduction =================
        double* sbuf = reinterpret_cast<double*>(sh);
        double sy2 = 0.0, st2n = 0.0, slogn = 0.0;
        const float* yrow = g_A + (size_t)Qq * Qq;
        for (int q = tid; q < Qq; q += 256) {
            float y = __ldcg(&yrow[q]);
            sy2 += (double)y * (double)y;
            int c = g_cnt[q];
            if (c > 0) {
                double tq = (double)g_t[q];
                st2n  += tq * tq / (double)c;
                slogn += log((double)c);
            }
        }
        double SY2 = block_reduce_d(sy2, sbuf);
        double ST  = block_reduce_d(st2n, sbuf);
        double SL  = block_reduce_d(slogn, sbuf);
        if (tid == 0) {
            double sumlogL = 0.0;
            for (int i = 0; i < NP; i++) sumlogL += g_logdiag[i];
            double e = (double)se[0], b = (double)sb[0];
            double sig2 = e + b;
            double sy = g_sums[0], sen = g_sums[1], sz2 = g_sums[2];
            double S1 = ST - SY2;
            double mld = 2.0 * sy + 2.0 * sen + (double)Nn * log(sig2) + (double)Nn * log(C2C);
            double quad = sig2 / e * (sz2 - S1);
            double logdetR = (double)Nn * log(e) + SL + 2.0 * sumlogL - (double)Nn * log(sig2);
            out[0] = (float)(mld + quad - sz2 + logdetR);
        }
        return;
    }

    // ================= worker blocks =================
    int w = bid - 1;
    int W = gridDim.x - 1;
    for (int kb = 0; kb < NP; kb++) {
        int nt0 = kb + 1;
        int m = NP - 1 - kb;
        int nsy = (m + 1) * (m + 2) / 2 - 1;     // pairs excl. (NP,NP)
        int njobs = m + (nsy > 0 ? nsy - 1 : 0); // m worker trsms + (nsy-1) worker syrks
        for (int job = w; job < njobs; job += W) {
            if (job < m) {
                // ---- trsm of tile bx = nt0+1+job against L(kb) ----
                int bx = nt0 + 1 + job;
                wait_ge(g_fL, kb + 1, 128);
                const float* Lk = g_A + (size_t)(kb * NB) * Qq + kb * NB;
                for (int i = tid; i < 4096; i += 256)
                    Pa[i >> 6][i & 63] = __ldcg(&Lk[(size_t)(i >> 6) * Qq + (i & 63)]);
                __syncthreads();
                if (tid < 64) buf2[0][tid] = __frcp_rn(Pa[tid][tid]);
                wait_eq(&g_gen[(bx * NP + kb) * FP], kb, 128);
                load_tile(Pb, bx, kb);
                __syncthreads();
                trsm64(Pa, Pb, buf2[0]);
                __syncthreads();
                store_tile(Pb, bx, kb);
                publish(&g_ftr[bx * FP], kb + 1);
            } else {
                // ---- regular syrk tile: pair index pj in by-major order ----
                int pj = 1 + (job - m);          // skip pj=0 (special diag)
                int t2 = pj, by = nt0, len = m + 1;
                while (t2 >= len) { t2 -= len; by++; len--; }
                int bx = by + t2;
                wait_ge(&g_ftr[bx * FP], kb + 1, 128);
                wait_ge(&g_ftr[by * FP], kb + 1, 128);
                wait_eq(&g_gen[(bx * NP + by) * FP], kb, 128);
                load_tile(Pa, bx, kb);
                load_tile(Pb, by, kb);
                __syncthreads();
                float acc[4][4];
                syrk_acc(Pa, Pb, acc);
                rmw_tile(bx, by, acc);
                publish(&g_gen[(bx * NP + by) * FP], kb + 1);
            }
        }
    }
}

// ---------------- launch ----------------
extern "C" void kernel_launch(void* const* d_in, const int* in_sizes, int n_in,
                              void* d_out, int out_size) {
    const float*     y_true = (const float*)d_in[0];
    const float*     y_pred = (const float*)d_in[1];
    const float*     sig2e  = (const float*)d_in[2];
    const float*     sig2bs = (const float*)d_in[3];
    const float*     ell    = (const float*)d_in[4];
    const float*     dist   = (const float*)d_in[5];
    const long long* Z_idx  = (const long long*)d_in[6];
    float* out = (float*)d_out;

    int nsm = 0;
    cudaDeviceGetAttribute(&nsm, cudaDevAttrMultiProcessorCount, 0);
    if (nsm <= 0) nsm = 148;
    int nblocks = 2 * nsm;   // co-resident via __launch_bounds__(256,2)

    k_pre<<<1, 1024>>>(y_true, y_pred, sig2e, sig2bs);
    k_acc<<<1, 1024>>>(Z_idx);
    int nbuild = ((Qq + 1) * Qq + 1023) / 1024;
    k_buildA<<<nbuild, 1024>>>(dist, sig2e, sig2bs, ell);

    k_chol<<<nblocks, 256>>>(sig2e, sig2bs, out);
}